// round 2
// baseline (speedup 1.0000x reference)
#include <cuda_runtime.h>
#include <cstdint>

// NMS_5549097746496: fused 8x8x8 MaxPool -> MaxUnpool -> threshold(0.5) -> (thresholded == x)
// Input:  raw [2,3,128,256,256] fp32   (B*C = 6, D=128, H=256, W=256; all divisible by 8 -> no pad)
// Output: mask as float32 0.0/1.0 (bool reference materialized as float by harness).
//
// Per element: t = (elem is block argmax (first-occurrence, K-order dz*64+dy*8+dx) && bmax > 0.5)
//                  ? bmax : 0.0f;   out = (t == x)
// At the argmax, t is bit-identical to x, so float equality is exact/faithful,
// including the "x == 0" quirk elsewhere.

#define NMS_THRESH 0.5f

__global__ __launch_bounds__(256, 4)
void nms_mask_kernel(const float* __restrict__ in, float* __restrict__ out) {
    // grid.x = BC * (D/8) * (H/8) = 6 * 16 * 32 = 3072
    const int W = 256;
    const int HW = 256 * 256;

    int tile = blockIdx.x;
    int hblk = tile & 31;          // 0..31  (H/8)
    int dblk = (tile >> 5) & 15;   // 0..15  (D/8)
    int bc   = tile >> 9;          // 0..5   (B*C)

    // base element offset of this CTA's 8(d) x 8(h) x 256(w) tile
    size_t base = ((size_t)bc * 128 + (size_t)dblk * 8) * HW + (size_t)hblk * 8 * W;

    int lane = threadIdx.x & 31;
    int warp = threadIdx.x >> 5;
    int dz   = lane & 7;                 // d-slice within window, also reduce-group member id
    int wblk = (lane >> 3) + warp * 4;   // 0..31 : which window along W
    int w0   = wblk * 8;

    const float* p = in + base + (size_t)dz * HW + w0;

    // ---- load 64 values (8 rows x 8 floats) into registers: 16x LDG.128 ----
    float4 va[8], vb[8];
    #pragma unroll
    for (int dy = 0; dy < 8; dy++) {
        va[dy] = *reinterpret_cast<const float4*>(p + dy * W);
        vb[dy] = *reinterpret_cast<const float4*>(p + dy * W + 4);
    }

    // ---- local max + argmax, first occurrence in K-order e = dz*64 + dy*8 + dx ----
    float best  = -__int_as_float(0x7f800000);  // -inf
    int   bestE = 0;
    #pragma unroll
    for (int dy = 0; dy < 8; dy++) {
        float v[8] = {va[dy].x, va[dy].y, va[dy].z, va[dy].w,
                      vb[dy].x, vb[dy].y, vb[dy].z, vb[dy].w};
        #pragma unroll
        for (int dx = 0; dx < 8; dx++) {
            // strict > keeps the first occurrence within this thread's slice
            if (v[dx] > best) { best = v[dx]; bestE = dz * 64 + dy * 8 + dx; }
        }
    }

    // ---- reduce across the 8 lanes of this window (xor 1,2,4 stays in lane-aligned group) ----
    #pragma unroll
    for (int m = 1; m < 8; m <<= 1) {
        float ov = __shfl_xor_sync(0xffffffffu, best,  m);
        int   oe = __shfl_xor_sync(0xffffffffu, bestE, m);
        // larger value wins; on exact tie, smaller e (first occurrence) wins
        if (ov > best || (ov == best && oe < bestE)) { best = ov; bestE = oe; }
    }

    const bool hot = best > NMS_THRESH;

    // ---- emit mask as float 0/1: 8 floats per row = two STG.128 ----
    float* q = out + base + (size_t)dz * HW + w0;
    #pragma unroll
    for (int dy = 0; dy < 8; dy++) {
        float v[8] = {va[dy].x, va[dy].y, va[dy].z, va[dy].w,
                      vb[dy].x, vb[dy].y, vb[dy].z, vb[dy].w};
        float m[8];
        #pragma unroll
        for (int dx = 0; dx < 8; dx++) {
            int   e = dz * 64 + dy * 8 + dx;
            float t = (hot && e == bestE) ? best : 0.0f;
            m[dx] = (t == v[dx]) ? 1.0f : 0.0f;
        }
        *reinterpret_cast<float4*>(q + dy * W)     = make_float4(m[0], m[1], m[2], m[3]);
        *reinterpret_cast<float4*>(q + dy * W + 4) = make_float4(m[4], m[5], m[6], m[7]);
    }
}

extern "C" void kernel_launch(void* const* d_in, const int* in_sizes, int n_in,
                              void* d_out, int out_size) {
    (void)in_sizes; (void)n_in; (void)out_size;
    const float* in = (const float*)d_in[0];
    float* out = (float*)d_out;
    // BC * D/8 * H/8 = 6 * 16 * 32 = 3072 CTAs, 256 threads each
    nms_mask_kernel<<<3072, 256>>>(in, out);
}

// round 4
// speedup vs baseline: 1.4162x; 1.4162x over previous
#include <cuda_runtime.h>
#include <cstdint>

// NMS_5549097746496: fused 8x8x8 MaxPool -> MaxUnpool -> threshold(0.5) -> (thresholded == x)
// Input:  raw [2,3,128,256,256] fp32 ; Output: mask as float32 0/1.
//
// Simplification: out[i] = (x[i]==0) ? 1 : 0 everywhere, EXCEPT the block-argmax
// position when bmax > 0.5, which is 1 (the unpooled value there is bit-identical to x).
// Phase 1 streams (x==0) with perfectly coalesced 512B warp transactions;
// phase 2 overwrites one element per hot window (same thread -> ordered stores).
//
// Layout: CTA = 256 thr = 8 warps; tile = 8(d) x 16(h) x 256(w).
//   warp  : warp_h = warp>>2 (h-window), warp_w = warp&3 (64-float w-span)
//   lane  : win = lane>>2 (window in span), dzh = (lane>>1)&1 (dz half), wc = lane&1 (16B chunk)
// Per load instruction: 2 dz-planes x 256B contiguous = 4 fully-used 128B lines.

#define NMS_THRESH 0.5f

__global__ __launch_bounds__(256)
void nms_mask_kernel(const float* __restrict__ in, float* __restrict__ out) {
    const int W = 256;
    const int HW = 256 * 256;

    int bid   = blockIdx.x;        // 6 * 16 * 16 = 1536
    int hpair = bid & 15;          // 16 h-window-pairs
    int dblk  = (bid >> 4) & 15;   // 16 d-windows
    int bc    = bid >> 8;          // 6

    int lane   = threadIdx.x & 31;
    int warp   = threadIdx.x >> 5;
    int warp_h = warp >> 2;        // 0..1
    int warp_w = warp & 3;         // 0..3
    int win    = lane >> 2;        // 0..7  window along w within warp span
    int dzh    = (lane >> 1) & 1;  // 0..1  dz half (dz = dzh*4 + dzl)
    int wc     = lane & 1;         // 0..1  16B chunk within window row (dx = wc*4 + j)

    // window-origin offset (dz=0,dy=0,dx=0) for this lane's window
    size_t wbase = ((size_t)(bc * 128 + dblk * 8)) * HW
                 + (size_t)(hpair * 16 + warp_h * 8) * W
                 + (size_t)(warp_w * 64 + win * 8);
    // this lane's chunk base
    size_t mybase = wbase + (size_t)dzh * 4 * HW + (size_t)wc * 4;

    const float* p = in  + mybase;
    float*       q = out + mybase;

    float best  = __int_as_float(0xff800000);  // -inf
    int   bestE = 1 << 30;

    #pragma unroll
    for (int dzl = 0; dzl < 4; dzl++) {
        #pragma unroll
        for (int dy = 0; dy < 8; dy++) {
            int off = dzl * HW + dy * W;
            float4 v = __ldcs(reinterpret_cast<const float4*>(p + off));

            float4 m;
            m.x = (v.x == 0.0f) ? 1.0f : 0.0f;
            m.y = (v.y == 0.0f) ? 1.0f : 0.0f;
            m.z = (v.z == 0.0f) ? 1.0f : 0.0f;
            m.w = (v.w == 0.0f) ? 1.0f : 0.0f;
            __stcs(reinterpret_cast<float4*>(q + off), m);

            int eb = (dzh * 4 + dzl) * 64 + dy * 8 + wc * 4;  // K-order index of v.x
            // full lexicographic comparator (value desc, e asc) -> order-independent
            if (v.x > best || (v.x == best && eb + 0 < bestE)) { best = v.x; bestE = eb + 0; }
            if (v.y > best || (v.y == best && eb + 1 < bestE)) { best = v.y; bestE = eb + 1; }
            if (v.z > best || (v.z == best && eb + 2 < bestE)) { best = v.z; bestE = eb + 2; }
            if (v.w > best || (v.w == best && eb + 3 < bestE)) { best = v.w; bestE = eb + 3; }
        }
    }

    // remember local candidate to identify the owning lane afterwards
    float lbest = best; int lE = bestE;

    // reduce across the 4 lanes of this window (xor 1,2 stays in aligned group of 4)
    #pragma unroll
    for (int msk = 1; msk < 4; msk <<= 1) {
        float ov = __shfl_xor_sync(0xffffffffu, best,  msk);
        int   oe = __shfl_xor_sync(0xffffffffu, bestE, msk);
        if (ov > best || (ov == best && oe < bestE)) { best = ov; bestE = oe; }
    }

    // phase 2: the lane that loaded the winning element rewrites it to 1.0 if hot.
    // K-index e is unique across the window, so exactly one lane matches.
    if (best > NMS_THRESH && lbest == best && lE == bestE) {
        int dz = bestE >> 6, dy = (bestE >> 3) & 7, dx = bestE & 7;
        out[wbase + (size_t)dz * HW + (size_t)dy * W + dx] = 1.0f;
    }
}

extern "C" void kernel_launch(void* const* d_in, const int* in_sizes, int n_in,
                              void* d_out, int out_size) {
    (void)in_sizes; (void)n_in; (void)out_size;
    const float* in = (const float*)d_in[0];
    float* out = (float*)d_out;
    // bc(6) * dblk(16) * hpair(16) = 1536 CTAs, 256 threads each
    nms_mask_kernel<<<1536, 256>>>(in, out);
}

// round 5
// speedup vs baseline: 1.6135x; 1.1394x over previous
#include <cuda_runtime.h>
#include <cstdint>

// NMS_5549097746496: fused 8x8x8 MaxPool -> MaxUnpool -> threshold(0.5) -> (thresholded == x)
// Input:  raw [2,3,128,256,256] fp32 ; Output: mask as float32 0/1.
//
// out[i] = (x[i]==0) ? 1 : 0 everywhere, EXCEPT the block-argmax position when
// bmax > 0.5, which is 1 (the unpooled value there is bit-identical to x).
// Phase 1 streams (x==0) with fully-coalesced transactions; phase 2 overwrites
// one element per hot window (same-thread program order -> correctly ordered).
//
// R4 change: explicitly stage one dz-plane (8 x float4) in registers before the
// store/compare pass, forcing 8 back-to-back LDGs (MLP=8) to cover DRAM latency.
//
// Layout: CTA = 256 thr = 8 warps; tile = 8(d) x 16(h) x 256(w).
//   warp  : warp_h = warp>>2 (h-window), warp_w = warp&3 (64-float w-span)
//   lane  : win = lane>>2, dzh = (lane>>1)&1, wc = lane&1
// Per load instruction: 2 dz-planes x 256B contiguous = 4 fully-used 128B lines.

#define NMS_THRESH 0.5f

__global__ __launch_bounds__(256, 4)
void nms_mask_kernel(const float* __restrict__ in, float* __restrict__ out) {
    const int W = 256;
    const int HW = 256 * 256;

    int bid   = blockIdx.x;        // 6 * 16 * 16 = 1536
    int hpair = bid & 15;          // 16 h-window-pairs
    int dblk  = (bid >> 4) & 15;   // 16 d-windows
    int bc    = bid >> 8;          // 6

    int lane   = threadIdx.x & 31;
    int warp   = threadIdx.x >> 5;
    int warp_h = warp >> 2;        // 0..1
    int warp_w = warp & 3;         // 0..3
    int win    = lane >> 2;        // 0..7  window along w within warp span
    int dzh    = (lane >> 1) & 1;  // 0..1  dz half (dz = dzh*4 + dzl)
    int wc     = lane & 1;         // 0..1  16B chunk within window row (dx = wc*4 + j)

    // window-origin offset (dz=0,dy=0,dx=0) for this lane's window
    size_t wbase = ((size_t)(bc * 128 + dblk * 8)) * HW
                 + (size_t)(hpair * 16 + warp_h * 8) * W
                 + (size_t)(warp_w * 64 + win * 8);
    // this lane's chunk base
    size_t mybase = wbase + (size_t)dzh * 4 * HW + (size_t)wc * 4;

    const float* p = in  + mybase;
    float*       q = out + mybase;

    float best  = __int_as_float(0xff800000);  // -inf
    int   bestE = 1 << 30;

    #pragma unroll
    for (int dzl = 0; dzl < 4; dzl++) {
        // ---- stage the whole dz-plane: 8 independent LDG.128 (MLP=8) ----
        float4 v[8];
        #pragma unroll
        for (int dy = 0; dy < 8; dy++)
            v[dy] = __ldcs(reinterpret_cast<const float4*>(p + dzl * HW + dy * W));

        // ---- emit mask + update running (max, argE) ----
        #pragma unroll
        for (int dy = 0; dy < 8; dy++) {
            float4 m;
            m.x = (v[dy].x == 0.0f) ? 1.0f : 0.0f;
            m.y = (v[dy].y == 0.0f) ? 1.0f : 0.0f;
            m.z = (v[dy].z == 0.0f) ? 1.0f : 0.0f;
            m.w = (v[dy].w == 0.0f) ? 1.0f : 0.0f;
            __stcs(reinterpret_cast<float4*>(q + dzl * HW + dy * W), m);

            int eb = (dzh * 4 + dzl) * 64 + dy * 8 + wc * 4;  // K-order index of v.x
            // full lexicographic comparator (value desc, e asc) -> order-independent
            if (v[dy].x > best || (v[dy].x == best && eb + 0 < bestE)) { best = v[dy].x; bestE = eb + 0; }
            if (v[dy].y > best || (v[dy].y == best && eb + 1 < bestE)) { best = v[dy].y; bestE = eb + 1; }
            if (v[dy].z > best || (v[dy].z == best && eb + 2 < bestE)) { best = v[dy].z; bestE = eb + 2; }
            if (v[dy].w > best || (v[dy].w == best && eb + 3 < bestE)) { best = v[dy].w; bestE = eb + 3; }
        }
    }

    // remember local candidate to identify the owning lane afterwards
    float lbest = best; int lE = bestE;

    // reduce across the 4 lanes of this window (xor 1,2 stays in aligned group of 4)
    #pragma unroll
    for (int msk = 1; msk < 4; msk <<= 1) {
        float ov = __shfl_xor_sync(0xffffffffu, best,  msk);
        int   oe = __shfl_xor_sync(0xffffffffu, bestE, msk);
        if (ov > best || (ov == best && oe < bestE)) { best = ov; bestE = oe; }
    }

    // phase 2: the lane that loaded the winning element rewrites it to 1.0 if hot.
    // K-index e is unique across the window, so exactly one lane matches.
    if (best > NMS_THRESH && lbest == best && lE == bestE) {
        int dz = bestE >> 6, dy = (bestE >> 3) & 7, dx = bestE & 7;
        out[wbase + (size_t)dz * HW + (size_t)dy * W + dx] = 1.0f;
    }
}

extern "C" void kernel_launch(void* const* d_in, const int* in_sizes, int n_in,
                              void* d_out, int out_size) {
    (void)in_sizes; (void)n_in; (void)out_size;
    const float* in = (const float*)d_in[0];
    float* out = (float*)d_out;
    // bc(6) * dblk(16) * hpair(16) = 1536 CTAs, 256 threads each
    nms_mask_kernel<<<1536, 256>>>(in, out);
}

// round 6
// speedup vs baseline: 1.6582x; 1.0277x over previous
#include <cuda_runtime.h>
#include <cstdint>

// NMS_5549097746496: fused 8x8x8 MaxPool -> MaxUnpool -> threshold(0.5) -> (thresholded == x)
// Input:  raw [2,3,128,256,256] fp32 ; Output: mask as float32 0/1.
//
// out[i] = (x[i]==0) ? 1 : 0 everywhere, EXCEPT the block-argmax position when
// bmax > 0.5, which is 1 (the unpooled value there is bit-identical to x).
// Phase 1 streams (x==0); phase 2 overwrites one element per hot window
// (same-thread program order -> correctly ordered).
//
// R5 change: tile halved along h -> 8(d) x 8(h) x 256(w), grid 1536 -> 3072.
// Halves T_CTA to shrink the ramp-down tail that capped DRAM at 69%.
// Regs ~48 -> 5 resident CTAs/SM (62% occ). Load staging (MLP=8) kept.
//
// Layout: CTA = 256 thr = 8 warps; 32 windows along w, 4 windows/warp.
//   lane: win = lane>>3 (window), dzp = (lane>>1)&3 (plane), wc = lane&1 (16B chunk)
// Per load instruction: 4 dz-planes x 128B contiguous = 4 fully-used 128B lines.

#define NMS_THRESH 0.5f

__global__ __launch_bounds__(256, 4)
void nms_mask_kernel(const float* __restrict__ in, float* __restrict__ out) {
    const int W = 256;
    const int HW = 256 * 256;

    int bid  = blockIdx.x;        // 6 * 16 * 32 = 3072
    int hblk = bid & 31;          // 32 h-windows
    int dblk = (bid >> 5) & 15;   // 16 d-windows
    int bc   = bid >> 9;          // 6

    int lane = threadIdx.x & 31;
    int warp = threadIdx.x >> 5;  // 0..7, each owns 4 windows (32-float span)
    int win  = lane >> 3;         // 0..3  window within warp span
    int dzp  = (lane >> 1) & 3;   // 0..3  plane within dz-half (dz = dzh*4 + dzp)
    int wc   = lane & 1;          // 0..1  16B chunk within window row

    // window-origin offset (dz=0,dy=0,dx=0) for this lane's window
    size_t wbase = ((size_t)(bc * 128 + dblk * 8)) * HW
                 + (size_t)(hblk * 8) * W
                 + (size_t)(warp * 32 + win * 8);
    // this lane's chunk base (dzh handled in the loop)
    size_t mybase = wbase + (size_t)dzp * HW + (size_t)wc * 4;

    const float* p = in  + mybase;
    float*       q = out + mybase;

    float best  = __int_as_float(0xff800000);  // -inf
    int   bestE = 1 << 30;

    #pragma unroll
    for (int dzh = 0; dzh < 2; dzh++) {
        const size_t ph = (size_t)dzh * 4 * HW;

        // ---- stage the whole plane: 8 independent LDG.128 (MLP=8) ----
        float4 v[8];
        #pragma unroll
        for (int dy = 0; dy < 8; dy++)
            v[dy] = __ldcs(reinterpret_cast<const float4*>(p + ph + dy * W));

        // ---- emit mask + update running (max, argE) ----
        #pragma unroll
        for (int dy = 0; dy < 8; dy++) {
            float4 m;
            m.x = (v[dy].x == 0.0f) ? 1.0f : 0.0f;
            m.y = (v[dy].y == 0.0f) ? 1.0f : 0.0f;
            m.z = (v[dy].z == 0.0f) ? 1.0f : 0.0f;
            m.w = (v[dy].w == 0.0f) ? 1.0f : 0.0f;
            __stcs(reinterpret_cast<float4*>(q + ph + dy * W), m);

            int eb = (dzh * 4 + dzp) * 64 + dy * 8 + wc * 4;  // K-order index of v.x
            // full lexicographic comparator (value desc, e asc) -> order-independent
            if (v[dy].x > best || (v[dy].x == best && eb + 0 < bestE)) { best = v[dy].x; bestE = eb + 0; }
            if (v[dy].y > best || (v[dy].y == best && eb + 1 < bestE)) { best = v[dy].y; bestE = eb + 1; }
            if (v[dy].z > best || (v[dy].z == best && eb + 2 < bestE)) { best = v[dy].z; bestE = eb + 2; }
            if (v[dy].w > best || (v[dy].w == best && eb + 3 < bestE)) { best = v[dy].w; bestE = eb + 3; }
        }
    }

    // remember local candidate to identify the owning lane afterwards
    float lbest = best; int lE = bestE;

    // reduce across the 8 lanes of this window (xor 1,2,4 stays in aligned group of 8)
    #pragma unroll
    for (int msk = 1; msk < 8; msk <<= 1) {
        float ov = __shfl_xor_sync(0xffffffffu, best,  msk);
        int   oe = __shfl_xor_sync(0xffffffffu, bestE, msk);
        if (ov > best || (ov == best && oe < bestE)) { best = ov; bestE = oe; }
    }

    // phase 2: the lane that loaded the winning element rewrites it to 1.0 if hot.
    // K-index e is unique across the window, so exactly one lane matches.
    if (best > NMS_THRESH && lbest == best && lE == bestE) {
        int dz = bestE >> 6, dy = (bestE >> 3) & 7, dx = bestE & 7;
        out[wbase + (size_t)dz * HW + (size_t)dy * W + dx] = 1.0f;
    }
}

extern "C" void kernel_launch(void* const* d_in, const int* in_sizes, int n_in,
                              void* d_out, int out_size) {
    (void)in_sizes; (void)n_in; (void)out_size;
    const float* in = (const float*)d_in[0];
    float* out = (float*)d_out;
    // bc(6) * dblk(16) * hblk(32) = 3072 CTAs, 256 threads each
    nms_mask_kernel<<<3072, 256>>>(in, out);
}